// round 14
// baseline (speedup 1.0000x reference)
#include <cuda_runtime.h>
#include <cuda_bf16.h>
#include <mma.h>
#include <cstdint>

using namespace nvcuda;

// ---------------------------------------------------------------------------
// Problem constants
// ---------------------------------------------------------------------------
#define BATCH   2048
#define SEQ     32
#define EMB     1024
#define HEADS   16
#define HSIZE   64
#define BT      (BATCH * SEQ)          // 65536 rows
#define QKV_N   (3 * EMB)              // 3072

// GEMM tiling
#define HBM   128                      // M per CTA
#define HBN   128                      // N per CTA
#define HBK   32                       // K per smem tile (bf16)
#define AROWE 32                       // A smem row stride elems (64 B, no pad)
#define AROWB 64
#define BROWE 40                       // B smem row stride elems (80 B, conflict-free)
#define BROWB 80
#define AMATB (128 * AROWB)            // 8192 B per A matrix tile
#define BMATB (128 * BROWB)            // 10240 B per B matrix tile
#define OFF_AH 0
#define OFF_AL (AMATB)                 // 8192
#define OFF_BH (2 * AMATB)             // 16384
#define OFF_BL (2 * AMATB + BMATB)     // 26624
#define STAGEB (2 * AMATB + 2 * BMATB) // 36864
#define NSTG  3
#define SMEMB (NSTG * STAGEB)          // 110592
#define NPHYS 32                       // physical K tiles (1024 / 32)

// ---------------------------------------------------------------------------
// Scratch (device globals; no dynamic allocation allowed)
// ---------------------------------------------------------------------------
__device__ float         g_qkv[(size_t)BT * QKV_N];     // fp32 Q|K|V
__device__ __nv_bfloat16 g_xh[(size_t)BT * EMB];
__device__ __nv_bfloat16 g_xl[(size_t)BT * EMB];
__device__ __nv_bfloat16 g_yh[(size_t)BT * EMB];
__device__ __nv_bfloat16 g_yl[(size_t)BT * EMB];
__device__ __nv_bfloat16 g_wqh[(size_t)QKV_N * EMB];    // W_qkv^T  [3072,1024]
__device__ __nv_bfloat16 g_wql[(size_t)QKV_N * EMB];
__device__ __nv_bfloat16 g_wph[(size_t)EMB * EMB];      // Wp^T     [1024,1024]
__device__ __nv_bfloat16 g_wpl[(size_t)EMB * EMB];

// ---------------------------------------------------------------------------
// PTX helpers (sm_80 baseline features only)
// ---------------------------------------------------------------------------
__device__ __forceinline__ uint32_t smem_to_u32(const void* p) {
    uint32_t a;
    asm("{ .reg .u64 t; cvta.to.shared.u64 t, %1; cvt.u32.u64 %0, t; }" : "=r"(a) : "l"(p));
    return a;
}
__device__ __forceinline__ void cp_async16(uint32_t dst, const void* src) {
    asm volatile("cp.async.cg.shared.global [%0], [%1], 16;" :: "r"(dst), "l"(src));
}
#define CP_COMMIT()  asm volatile("cp.async.commit_group;" ::: "memory")
#define CP_WAIT(n)   asm volatile("cp.async.wait_group %0;" :: "n"(n) : "memory")

// ---------------------------------------------------------------------------
// fp32 -> (bf16 hi, bf16 lo) split helpers
// ---------------------------------------------------------------------------
__device__ __forceinline__ void split1(float v, __nv_bfloat16& h, __nv_bfloat16& l) {
    h = __float2bfloat16(v);
    l = __float2bfloat16(v - __bfloat162float(h));
}

__global__ void split_x_kernel(const float4* __restrict__ in,
                               __nv_bfloat162* __restrict__ hi,
                               __nv_bfloat162* __restrict__ lo, int n4) {
    int i = blockIdx.x * 256 + threadIdx.x;
    if (i >= n4) return;
    float4 v = in[i];
    __nv_bfloat16 h0, h1, h2, h3, l0, l1, l2, l3;
    split1(v.x, h0, l0); split1(v.y, h1, l1);
    split1(v.z, h2, l2); split1(v.w, h3, l3);
    hi[2 * i]     = __nv_bfloat162(h0, h1);
    hi[2 * i + 1] = __nv_bfloat162(h2, h3);
    lo[2 * i]     = __nv_bfloat162(l0, l1);
    lo[2 * i + 1] = __nv_bfloat162(l2, l3);
}

// Pack W_qkv^T: row n (0..3071) of [N,K]: n -> (s,h,d); out[n][k] = W_s[h,k,d]
__global__ void pack_wqkv_kernel(const float* __restrict__ Wq,
                                 const float* __restrict__ Wk,
                                 const float* __restrict__ Wv,
                                 __nv_bfloat16* __restrict__ hi,
                                 __nv_bfloat16* __restrict__ lo) {
    int idx = blockIdx.x * 256 + threadIdx.x;
    if (idx >= QKV_N * EMB) return;
    int n = idx >> 10;
    int k = idx & 1023;
    int s = n >> 10;
    int r = n & 1023;
    int h = r >> 6;
    int d = r & 63;
    const float* W = (s == 0) ? Wq : ((s == 1) ? Wk : Wv);
    float v = W[((size_t)(h << 10) + k) * HSIZE + d];
    __nv_bfloat16 bh, bl;
    split1(v, bh, bl);
    hi[idx] = bh;
    lo[idx] = bl;
}

// Pack Wp^T: out[n][k] = Wp[k][n]
__global__ void pack_wp_kernel(const float* __restrict__ Wp,
                               __nv_bfloat16* __restrict__ hi,
                               __nv_bfloat16* __restrict__ lo) {
    int idx = blockIdx.x * 256 + threadIdx.x;
    if (idx >= EMB * EMB) return;
    int n = idx >> 10;
    int k = idx & 1023;
    float v = Wp[((size_t)k << 10) + n];
    __nv_bfloat16 bh, bl;
    split1(v, bh, bl);
    hi[idx] = bh;
    lo[idx] = bl;
}

// ---------------------------------------------------------------------------
// WMMA split-bf16 GEMM (3-term fused per physical K-tile):
//   C[M, Ncols] = Ah*Bh^T + Ah*Bl^T + Al*Bh^T   (+ bias), fp32 accumulate.
// A*: [M, 1024] bf16 row-major. B*: [Ncols, 1024] bf16 row-major.
// CTA tile 128x128, BK=32, 32 physical K-tiles, cp.async 3-STAGE pipeline
// (loads 2 tiles deep, ONE __syncthreads per tile), 8 warps (4m x 2n).
// ---------------------------------------------------------------------------
__global__ __launch_bounds__(256, 2)
void wgemm3_kernel(const __nv_bfloat16* __restrict__ Ah,
                   const __nv_bfloat16* __restrict__ Al,
                   const __nv_bfloat16* __restrict__ Bh,
                   const __nv_bfloat16* __restrict__ Bl,
                   float* __restrict__ C,
                   const float* __restrict__ bias,
                   int Ncols) {
    extern __shared__ __align__(16) char smem[];

    const int tid  = threadIdx.x;
    const int wid  = tid >> 5;
    const int lane = tid & 31;
    const int wm   = wid >> 1;     // 0..3  (m)
    const int wn   = wid & 1;      // 0..1  (n)
    const int m0   = blockIdx.y * HBM;
    const int n0   = blockIdx.x * HBN;

    const uint32_t sb32 = smem_to_u32(smem);

    wmma::fragment<wmma::accumulator, 16, 16, 16, float> acc[2][4];
#pragma unroll
    for (int i = 0; i < 2; i++)
#pragma unroll
        for (int j = 0; j < 4; j++) wmma::fill_fragment(acc[i][j], 0.f);

    // Per-thread cp.async slots: slot = tid + i*256 (512 slots):
    // row = slot>>2 (0..127), chunk = slot&3 (16B each), covers one 128x32 tile.
    const int rA = tid >> 2, cA = tid & 3;

    auto issue_stage = [&](int t, int s) {
        const int tk = t << 5;    // physical k offset
        const uint32_t stg = sb32 + s * STAGEB;
#pragma unroll
        for (int i = 0; i < 2; i++) {
            const int row = rA + i * 64;
            const uint32_t da = (uint32_t)(row * AROWB + cA * 16);
            const uint32_t db = (uint32_t)(row * BROWB + cA * 16);
            const size_t aoff = ((size_t)(m0 + row) << 10) + tk + (cA << 3);
            const size_t boff = ((size_t)(n0 + row) << 10) + tk + (cA << 3);
            cp_async16(stg + OFF_AH + da, Ah + aoff);
            cp_async16(stg + OFF_AL + da, Al + aoff);
            cp_async16(stg + OFF_BH + db, Bh + boff);
            cp_async16(stg + OFF_BL + db, Bl + boff);
        }
        CP_COMMIT();
    };

    // Prologue: fill stages 0 and 1 (loads run 2 tiles deep).
    issue_stage(0, 0);
    issue_stage(1, 1);

    int s = 0;                 // stage of tile t
    for (int t = 0; t < NPHYS; t++) {
        // Wait for tile t's group (issued 2 iterations ago); keep t+1 in flight.
        if (t + 1 < NPHYS) { CP_WAIT(1); } else { CP_WAIT(0); }
        __syncthreads();
        // Stage (t+2)%3 was last computed at t-1, finished before this barrier.
        if (t + 2 < NPHYS) {
            int s2 = s + 2; if (s2 >= NSTG) s2 -= NSTG;
            issue_stage(t + 2, s2);
        }

        const __nv_bfloat16* sAh = (const __nv_bfloat16*)(smem + s * STAGEB + OFF_AH);
        const __nv_bfloat16* sAl = (const __nv_bfloat16*)(smem + s * STAGEB + OFF_AL);
        const __nv_bfloat16* sBh = (const __nv_bfloat16*)(smem + s * STAGEB + OFF_BH);
        const __nv_bfloat16* sBl = (const __nv_bfloat16*)(smem + s * STAGEB + OFF_BL);

#pragma unroll
        for (int ks = 0; ks < 2; ks++) {
            const int k0 = ks << 4;
            wmma::fragment<wmma::matrix_a, 16, 16, 16, __nv_bfloat16, wmma::row_major> ahf[2], alf[2];
#pragma unroll
            for (int mt = 0; mt < 2; mt++) {
                wmma::load_matrix_sync(ahf[mt], sAh + (wm * 32 + mt * 16) * AROWE + k0, AROWE);
                wmma::load_matrix_sync(alf[mt], sAl + (wm * 32 + mt * 16) * AROWE + k0, AROWE);
            }
#pragma unroll
            for (int ng = 0; ng < 4; ng++) {
                wmma::fragment<wmma::matrix_b, 16, 16, 16, __nv_bfloat16, wmma::col_major> bhf, blf;
                wmma::load_matrix_sync(bhf, sBh + (wn * 64 + ng * 16) * BROWE + k0, BROWE);
                wmma::load_matrix_sync(blf, sBl + (wn * 64 + ng * 16) * BROWE + k0, BROWE);
#pragma unroll
                for (int mt = 0; mt < 2; mt++) {
                    wmma::mma_sync(acc[mt][ng], ahf[mt], bhf, acc[mt][ng]);  // Ah*Bh
                    wmma::mma_sync(acc[mt][ng], ahf[mt], blf, acc[mt][ng]);  // Ah*Bl
                    wmma::mma_sync(acc[mt][ng], alf[mt], bhf, acc[mt][ng]);  // Al*Bh
                }
            }
        }
        if (++s >= NSTG) s = 0;
    }

    // Epilogue
    if (bias == nullptr) {
#pragma unroll
        for (int mt = 0; mt < 2; mt++)
#pragma unroll
            for (int ng = 0; ng < 4; ng++) {
                int r0 = m0 + wm * 32 + mt * 16;
                int c0 = n0 + wn * 64 + ng * 16;
                wmma::store_matrix_sync(C + (size_t)r0 * Ncols + c0,
                                        acc[mt][ng], Ncols, wmma::mem_row_major);
            }
    } else {
        // Per-warp smem staging (aliases tile buffers -> barrier first)
        __syncthreads();
        float* stg = (float*)(smem) + wid * 16 * 20;   // 16x16 tile, ld=20
#pragma unroll
        for (int mt = 0; mt < 2; mt++)
#pragma unroll
            for (int ng = 0; ng < 4; ng++) {
                wmma::store_matrix_sync(stg, acc[mt][ng], 20, wmma::mem_row_major);
                __syncwarp();
                int r0 = m0 + wm * 32 + mt * 16;
                int c0 = n0 + wn * 64 + ng * 16;
                int rr = lane >> 1;
                int ch = (lane & 1) << 3;              // 0 or 8
                float4 v0, v1;
                const float* srow = stg + rr * 20 + ch;
                v0.x = srow[0] + bias[c0 + ch + 0];
                v0.y = srow[1] + bias[c0 + ch + 1];
                v0.z = srow[2] + bias[c0 + ch + 2];
                v0.w = srow[3] + bias[c0 + ch + 3];
                v1.x = srow[4] + bias[c0 + ch + 4];
                v1.y = srow[5] + bias[c0 + ch + 5];
                v1.z = srow[6] + bias[c0 + ch + 6];
                v1.w = srow[7] + bias[c0 + ch + 7];
                *(float4*)(C + (size_t)(r0 + rr) * Ncols + c0 + ch)     = v0;
                *(float4*)(C + (size_t)(r0 + rr) * Ncols + c0 + ch + 4) = v1;
                __syncwarp();
            }
    }
}

// ---------------------------------------------------------------------------
// Attention core: one block per (batch, head). 128 threads.
// qkv: [BT, 3072] fp32. Output: hi/lo bf16 head-concat [BT, 1024].
// ---------------------------------------------------------------------------
__global__ __launch_bounds__(128)
void attn_kernel(const float* __restrict__ qkv,
                 __nv_bfloat16* __restrict__ yh,
                 __nv_bfloat16* __restrict__ yl) {
    __shared__ float qs[SEQ][HSIZE + 1];
    __shared__ float ks[SEQ][HSIZE + 1];
    __shared__ float vs[SEQ][HSIZE + 1];
    __shared__ float ss[SEQ][SEQ + 1];

    const int bh = blockIdx.x;
    const int b  = bh >> 4;
    const int h  = bh & 15;
    const int tid = threadIdx.x;

    const float* base = qkv + (size_t)b * SEQ * QKV_N + h * HSIZE;

    for (int idx = tid; idx < SEQ * HSIZE; idx += 128) {
        int t = idx >> 6;
        int d = idx & 63;
        const float* rp = base + (size_t)t * QKV_N + d;
        qs[t][d] = rp[0];
        ks[t][d] = rp[EMB];
        vs[t][d] = rp[2 * EMB];
    }
    __syncthreads();

    for (int e = tid; e < SEQ * SEQ; e += 128) {
        int i = e >> 5;
        int j = e & 31;
        float acc = 0.f;
        if (j <= i) {
#pragma unroll
            for (int d = 0; d < HSIZE; d++) acc += qs[i][d] * ks[j][d];
            acc *= 0.125f;
        }
        ss[i][j] = acc;
    }
    __syncthreads();

    if (tid < SEQ) {
        const int i = tid;
        float mx = -1e30f;
        for (int j = 0; j <= i; j++) mx = fmaxf(mx, ss[i][j]);
        float sum = 0.f;
        for (int j = 0; j <= i; j++) {
            float ev = __expf(ss[i][j] - mx);
            ss[i][j] = ev;
            sum += ev;
        }
        float inv = 1.f / sum;
        for (int j = 0; j <= i; j++) ss[i][j] *= inv;
        for (int j = i + 1; j < SEQ; j++) ss[i][j] = 0.f;
    }
    __syncthreads();

    for (int idx = tid; idx < SEQ * HSIZE; idx += 128) {
        int i = idx >> 6;
        int d = idx & 63;
        float acc = 0.f;
#pragma unroll
        for (int j = 0; j < SEQ; j++) acc += ss[i][j] * vs[j][d];
        size_t off = ((size_t)b * SEQ + i) * EMB + h * HSIZE + d;
        __nv_bfloat16 hv, lv;
        split1(acc, hv, lv);
        yh[off] = hv;
        yl[off] = lv;
    }
}

// ---------------------------------------------------------------------------
// Launch
// ---------------------------------------------------------------------------
extern "C" void kernel_launch(void* const* d_in, const int* in_sizes, int n_in,
                              void* d_out, int out_size) {
    const float* x  = (const float*)d_in[0];   // [2048, 32, 1024]
    const float* Wq = (const float*)d_in[1];   // [16, 1024, 64]
    const float* Wk = (const float*)d_in[2];
    const float* Wv = (const float*)d_in[3];
    const float* Wp = (const float*)d_in[4];   // [1024, 1024]
    const float* bp = (const float*)d_in[5];   // [1024]
    float* out = (float*)d_out;                // [2048, 32, 1024]

    float* qkv;            cudaGetSymbolAddress((void**)&qkv, g_qkv);
    __nv_bfloat16 *xh, *xl, *yh, *yl, *wqh, *wql, *wph, *wpl;
    cudaGetSymbolAddress((void**)&xh,  g_xh);
    cudaGetSymbolAddress((void**)&xl,  g_xl);
    cudaGetSymbolAddress((void**)&yh,  g_yh);
    cudaGetSymbolAddress((void**)&yl,  g_yl);
    cudaGetSymbolAddress((void**)&wqh, g_wqh);
    cudaGetSymbolAddress((void**)&wql, g_wql);
    cudaGetSymbolAddress((void**)&wph, g_wph);
    cudaGetSymbolAddress((void**)&wpl, g_wpl);

    cudaFuncSetAttribute(wgemm3_kernel,
                         cudaFuncAttributeMaxDynamicSharedMemorySize, SMEMB);

    // 0. Split x into bf16 hi/lo
    {
        int n4 = (BT * EMB) / 4;
        split_x_kernel<<<n4 / 256, 256>>>((const float4*)x,
                                          (__nv_bfloat162*)xh, (__nv_bfloat162*)xl, n4);
    }
    // 1. Pack weight transposes (hi/lo)
    pack_wqkv_kernel<<<(QKV_N * EMB) / 256, 256>>>(Wq, Wk, Wv, wqh, wql);
    pack_wp_kernel<<<(EMB * EMB) / 256, 256>>>(Wp, wph, wpl);

    // 2. QKV projection: [65536,1024] x [1024,3072] -> fp32 qkv
    {
        dim3 grid(QKV_N / HBN, BT / HBM);   // (24, 512)
        wgemm3_kernel<<<grid, 256, SMEMB>>>(xh, xl, wqh, wql, qkv, nullptr, QKV_N);
    }
    // 3. Attention per (b, h); emits hi/lo bf16 directly
    attn_kernel<<<BATCH * HEADS, 128>>>(qkv, yh, yl);

    // 4. Output projection + bias: [65536,1024] x [1024,1024] -> out
    {
        dim3 grid(EMB / HBN, BT / HBM);     // (8, 512)
        wgemm3_kernel<<<grid, 256, SMEMB>>>(yh, yl, wph, wpl, out, bp, EMB);
    }
}

// round 15
// speedup vs baseline: 2.3175x; 2.3175x over previous
#include <cuda_runtime.h>
#include <cuda_fp16.h>
#include <mma.h>
#include <cstdint>

using namespace nvcuda;

// ---------------------------------------------------------------------------
// Problem constants
// ---------------------------------------------------------------------------
#define BATCH   2048
#define SEQ     32
#define EMB     1024
#define HEADS   16
#define HSIZE   64
#define BT      (BATCH * SEQ)          // 65536 rows
#define QKV_N   (3 * EMB)              // 3072

// GEMM tiling (fp16 single-pass)
#define HBM   128                      // M per CTA
#define HBN   128                      // N per CTA
#define HBK   64                       // K per smem tile (fp16) = 128 B rows
#define ROWE  72                       // smem row stride elems (144 B; 36 words == 4 mod 32 -> LDSM conflict-free)
#define ROWB  144
#define MATB  (128 * ROWB)             // 18432 B per matrix tile
#define STAGEB (2 * MATB)              // A | B = 36864 B
#define SMEMB  (2 * STAGEB)            // 2 stages = 73728 B
#define NPHYS 16                       // K tiles (1024 / 64)

// ---------------------------------------------------------------------------
// Scratch (device globals; no dynamic allocation allowed)
// ---------------------------------------------------------------------------
__device__ float  g_qkv[(size_t)BT * QKV_N];   // fp32 Q|K|V
__device__ __half g_xh[(size_t)BT * EMB];      // x, fp16
__device__ __half g_yh[(size_t)BT * EMB];      // attention out, fp16
__device__ __half g_wqh[(size_t)QKV_N * EMB];  // W_qkv^T [3072,1024] fp16
__device__ __half g_wph[(size_t)EMB * EMB];    // Wp^T    [1024,1024] fp16

// ---------------------------------------------------------------------------
// PTX helpers (sm_80 baseline features only)
// ---------------------------------------------------------------------------
__device__ __forceinline__ uint32_t smem_to_u32(const void* p) {
    uint32_t a;
    asm("{ .reg .u64 t; cvta.to.shared.u64 t, %1; cvt.u32.u64 %0, t; }" : "=r"(a) : "l"(p));
    return a;
}
__device__ __forceinline__ void cp_async16(uint32_t dst, const void* src) {
    asm volatile("cp.async.cg.shared.global [%0], [%1], 16;" :: "r"(dst), "l"(src));
}
#define CP_COMMIT()  asm volatile("cp.async.commit_group;" ::: "memory")
#define CP_WAIT(n)   asm volatile("cp.async.wait_group %0;" :: "n"(n) : "memory")

// ---------------------------------------------------------------------------
// Producer kernels: round everything the GEMMs consume to fp16.
// ---------------------------------------------------------------------------
__global__ void round_x_kernel(const float4* __restrict__ in,
                               __half2* __restrict__ out, int n4) {
    int i = blockIdx.x * 256 + threadIdx.x;
    if (i >= n4) return;
    float4 v = in[i];
    out[2 * i]     = __floats2half2_rn(v.x, v.y);
    out[2 * i + 1] = __floats2half2_rn(v.z, v.w);
}

// Pack W_qkv^T: row n (0..3071) of [N,K]: n -> (s,h,d); out[n][k] = fp16(W_s[h,k,d])
__global__ void pack_wqkv_kernel(const float* __restrict__ Wq,
                                 const float* __restrict__ Wk,
                                 const float* __restrict__ Wv,
                                 __half* __restrict__ out) {
    int idx = blockIdx.x * 256 + threadIdx.x;
    if (idx >= QKV_N * EMB) return;
    int n = idx >> 10;
    int k = idx & 1023;
    int s = n >> 10;
    int r = n & 1023;
    int h = r >> 6;
    int d = r & 63;
    const float* W = (s == 0) ? Wq : ((s == 1) ? Wk : Wv);
    out[idx] = __float2half_rn(W[((size_t)(h << 10) + k) * HSIZE + d]);
}

// Pack Wp^T: out[n][k] = fp16(Wp[k][n])
__global__ void pack_wp_kernel(const float* __restrict__ Wp,
                               __half* __restrict__ out) {
    int idx = blockIdx.x * 256 + threadIdx.x;
    if (idx >= EMB * EMB) return;
    int n = idx >> 10;
    int k = idx & 1023;
    out[idx] = __float2half_rn(Wp[((size_t)k << 10) + n]);
}

// ---------------------------------------------------------------------------
// fp16 WMMA GEMM: C[M, Ncols] = A * B^T (+ bias), fp32 accumulate.
// A: [M, 1024] fp16 row-major. B: [Ncols, 1024] fp16 row-major.
// CTA tile 128x128, BK=64, 16 K-tiles, cp.async 2-stage pipeline
// (R9-proven issue-then-wait structure), 8 warps (4m x 2n), warp tile 32x64.
// ---------------------------------------------------------------------------
__global__ __launch_bounds__(256, 2)
void hgemm_kernel(const __half* __restrict__ A,
                  const __half* __restrict__ B,
                  float* __restrict__ C,
                  const float* __restrict__ bias,
                  int Ncols) {
    extern __shared__ __align__(16) char smem[];

    const int tid  = threadIdx.x;
    const int wid  = tid >> 5;
    const int lane = tid & 31;
    const int wm   = wid >> 1;     // 0..3  (m)
    const int wn   = wid & 1;      // 0..1  (n)
    const int m0   = blockIdx.y * HBM;
    const int n0   = blockIdx.x * HBN;

    const uint32_t sb32 = smem_to_u32(smem);

    wmma::fragment<wmma::accumulator, 16, 16, 16, float> acc[2][4];
#pragma unroll
    for (int i = 0; i < 2; i++)
#pragma unroll
        for (int j = 0; j < 4; j++) wmma::fill_fragment(acc[i][j], 0.f);

    // cp.async mapping: per matrix, 128 rows x 8 chunks(16B) = 1024 slots.
    // Thread covers slots {tid + i*256 : i=0..3}: row = slot>>3, chunk = slot&7.
    const int rA = tid >> 3;       // 0..31
    const int cA = tid & 7;        // 0..7

    auto issue_stage = [&](int t, int s) {
        const int tk = t << 6;     // k offset (elements)
        const uint32_t stg = sb32 + s * STAGEB;
#pragma unroll
        for (int i = 0; i < 4; i++) {
            const int row = rA + i * 32;
            const uint32_t doff = (uint32_t)(row * ROWB + cA * 16);
            cp_async16(stg + doff,
                       A + ((size_t)(m0 + row) << 10) + tk + (cA << 3));
            cp_async16(stg + MATB + doff,
                       B + ((size_t)(n0 + row) << 10) + tk + (cA << 3));
        }
        CP_COMMIT();
    };

    issue_stage(0, 0);

    for (int t = 0; t < NPHYS; t++) {
        const int s = t & 1;
        if (t + 1 < NPHYS) {
            issue_stage(t + 1, s ^ 1);
            CP_WAIT(1);
        } else {
            CP_WAIT(0);
        }
        __syncthreads();

        const __half* sA = (const __half*)(smem + s * STAGEB);
        const __half* sB = (const __half*)(smem + s * STAGEB + MATB);

#pragma unroll
        for (int ks = 0; ks < 4; ks++) {
            const int k0 = ks << 4;
            wmma::fragment<wmma::matrix_a, 16, 16, 16, __half, wmma::row_major> af[2];
#pragma unroll
            for (int mt = 0; mt < 2; mt++)
                wmma::load_matrix_sync(af[mt],
                    sA + (wm * 32 + mt * 16) * ROWE + k0, ROWE);
#pragma unroll
            for (int ng = 0; ng < 4; ng++) {
                wmma::fragment<wmma::matrix_b, 16, 16, 16, __half, wmma::col_major> bf;
                wmma::load_matrix_sync(bf,
                    sB + (wn * 64 + ng * 16) * ROWE + k0, ROWE);
#pragma unroll
                for (int mt = 0; mt < 2; mt++)
                    wmma::mma_sync(acc[mt][ng], af[mt], bf, acc[mt][ng]);
            }
        }
        __syncthreads();
    }

    // Epilogue
    if (bias == nullptr) {
#pragma unroll
        for (int mt = 0; mt < 2; mt++)
#pragma unroll
            for (int ng = 0; ng < 4; ng++) {
                int r0 = m0 + wm * 32 + mt * 16;
                int c0 = n0 + wn * 64 + ng * 16;
                wmma::store_matrix_sync(C + (size_t)r0 * Ncols + c0,
                                        acc[mt][ng], Ncols, wmma::mem_row_major);
            }
    } else {
        // Per-warp smem staging (aliased onto tile buffers; safe after final sync)
        float* stg = (float*)(smem) + wid * 16 * 20;   // 16x16 tile, ld=20
#pragma unroll
        for (int mt = 0; mt < 2; mt++)
#pragma unroll
            for (int ng = 0; ng < 4; ng++) {
                wmma::store_matrix_sync(stg, acc[mt][ng], 20, wmma::mem_row_major);
                __syncwarp();
                int r0 = m0 + wm * 32 + mt * 16;
                int c0 = n0 + wn * 64 + ng * 16;
                int rr = lane >> 1;
                int ch = (lane & 1) << 3;              // 0 or 8
                float4 v0, v1;
                const float* srow = stg + rr * 20 + ch;
                v0.x = srow[0] + bias[c0 + ch + 0];
                v0.y = srow[1] + bias[c0 + ch + 1];
                v0.z = srow[2] + bias[c0 + ch + 2];
                v0.w = srow[3] + bias[c0 + ch + 3];
                v1.x = srow[4] + bias[c0 + ch + 4];
                v1.y = srow[5] + bias[c0 + ch + 5];
                v1.z = srow[6] + bias[c0 + ch + 6];
                v1.w = srow[7] + bias[c0 + ch + 7];
                *(float4*)(C + (size_t)(r0 + rr) * Ncols + c0 + ch)     = v0;
                *(float4*)(C + (size_t)(r0 + rr) * Ncols + c0 + ch + 4) = v1;
                __syncwarp();
            }
    }
}

// ---------------------------------------------------------------------------
// Attention core: one block per (batch, head). 128 threads.
// qkv: [BT, 3072] fp32. Output: fp16 head-concat [BT, 1024].
// ---------------------------------------------------------------------------
__global__ __launch_bounds__(128)
void attn_kernel(const float* __restrict__ qkv,
                 __half* __restrict__ yh) {
    __shared__ float qs[SEQ][HSIZE + 1];
    __shared__ float ks[SEQ][HSIZE + 1];
    __shared__ float vs[SEQ][HSIZE + 1];
    __shared__ float ss[SEQ][SEQ + 1];

    const int bh = blockIdx.x;
    const int b  = bh >> 4;
    const int h  = bh & 15;
    const int tid = threadIdx.x;

    const float* base = qkv + (size_t)b * SEQ * QKV_N + h * HSIZE;

    for (int idx = tid; idx < SEQ * HSIZE; idx += 128) {
        int t = idx >> 6;
        int d = idx & 63;
        const float* rp = base + (size_t)t * QKV_N + d;
        qs[t][d] = rp[0];
        ks[t][d] = rp[EMB];
        vs[t][d] = rp[2 * EMB];
    }
    __syncthreads();

    for (int e = tid; e < SEQ * SEQ; e += 128) {
        int i = e >> 5;
        int j = e & 31;
        float acc = 0.f;
        if (j <= i) {
#pragma unroll
            for (int d = 0; d < HSIZE; d++) acc += qs[i][d] * ks[j][d];
            acc *= 0.125f;
        }
        ss[i][j] = acc;
    }
    __syncthreads();

    if (tid < SEQ) {
        const int i = tid;
        float mx = -1e30f;
        for (int j = 0; j <= i; j++) mx = fmaxf(mx, ss[i][j]);
        float sum = 0.f;
        for (int j = 0; j <= i; j++) {
            float ev = __expf(ss[i][j] - mx);
            ss[i][j] = ev;
            sum += ev;
        }
        float inv = 1.f / sum;
        for (int j = 0; j <= i; j++) ss[i][j] *= inv;
        for (int j = i + 1; j < SEQ; j++) ss[i][j] = 0.f;
    }
    __syncthreads();

    for (int idx = tid; idx < SEQ * HSIZE; idx += 128) {
        int i = idx >> 6;
        int d = idx & 63;
        float acc = 0.f;
#pragma unroll
        for (int j = 0; j < SEQ; j++) acc += ss[i][j] * vs[j][d];
        yh[((size_t)b * SEQ + i) * EMB + h * HSIZE + d] = __float2half_rn(acc);
    }
}

// ---------------------------------------------------------------------------
// Launch
// ---------------------------------------------------------------------------
extern "C" void kernel_launch(void* const* d_in, const int* in_sizes, int n_in,
                              void* d_out, int out_size) {
    const float* x  = (const float*)d_in[0];   // [2048, 32, 1024]
    const float* Wq = (const float*)d_in[1];   // [16, 1024, 64]
    const float* Wk = (const float*)d_in[2];
    const float* Wv = (const float*)d_in[3];
    const float* Wp = (const float*)d_in[4];   // [1024, 1024]
    const float* bp = (const float*)d_in[5];   // [1024]
    float* out = (float*)d_out;                // [2048, 32, 1024]

    float* qkv;  cudaGetSymbolAddress((void**)&qkv, g_qkv);
    __half *xh, *yh, *wqh, *wph;
    cudaGetSymbolAddress((void**)&xh,  g_xh);
    cudaGetSymbolAddress((void**)&yh,  g_yh);
    cudaGetSymbolAddress((void**)&wqh, g_wqh);
    cudaGetSymbolAddress((void**)&wph, g_wph);

    cudaFuncSetAttribute(hgemm_kernel,
                         cudaFuncAttributeMaxDynamicSharedMemorySize, SMEMB);

    // 0. Round x to fp16
    {
        int n4 = (BT * EMB) / 4;
        round_x_kernel<<<n4 / 256, 256>>>((const float4*)x, (__half2*)xh, n4);
    }
    // 1. Pack weight transposes (fp16)
    pack_wqkv_kernel<<<(QKV_N * EMB) / 256, 256>>>(Wq, Wk, Wv, wqh);
    pack_wp_kernel<<<(EMB * EMB) / 256, 256>>>(Wp, wph);

    // 2. QKV projection: [65536,1024] x [1024,3072] -> fp32 qkv
    {
        dim3 grid(QKV_N / HBN, BT / HBM);   // (24, 512)
        hgemm_kernel<<<grid, 256, SMEMB>>>(xh, wqh, qkv, nullptr, QKV_N);
    }
    // 3. Attention per (b, h); emits fp16 directly
    attn_kernel<<<BATCH * HEADS, 128>>>(qkv, yh);

    // 4. Output projection + bias: [65536,1024] x [1024,1024] -> out
    {
        dim3 grid(EMB / HBN, BT / HBM);     // (8, 512)
        hgemm_kernel<<<grid, 256, SMEMB>>>(yh, wph, out, bp, EMB);
    }
}

// round 16
// speedup vs baseline: 2.5029x; 1.0800x over previous
#include <cuda_runtime.h>
#include <cuda_fp16.h>
#include <mma.h>
#include <cstdint>

using namespace nvcuda;

// ---------------------------------------------------------------------------
// Problem constants
// ---------------------------------------------------------------------------
#define BATCH   2048
#define SEQ     32
#define EMB     1024
#define HEADS   16
#define HSIZE   64
#define BT      (BATCH * SEQ)          // 65536 rows
#define QKV_N   (3 * EMB)              // 3072

// GEMM tiling (fp16 single-pass)
#define HBM   128                      // M per CTA
#define HBN   128                      // N per CTA
#define HBK   64                       // K per smem tile (fp16) = 128 B rows
#define ROWE  72                       // smem row stride elems (144 B; conflict-free LDSM)
#define ROWB  144
#define MATB  (128 * ROWB)             // 18432 B per matrix tile
#define STAGEB (2 * MATB)              // A | B = 36864 B
#define SMEMB  (2 * STAGEB)            // 2 stages = 73728 B
#define NPHYS 16                       // K tiles (1024 / 64)

// ---------------------------------------------------------------------------
// Scratch (device globals; no dynamic allocation allowed)
// ---------------------------------------------------------------------------
__device__ __half g_qkvh[(size_t)BT * QKV_N];  // fp16 Q|K|V (GEMM1 output)
__device__ __half g_xh[(size_t)BT * EMB];      // x, fp16
__device__ __half g_yh[(size_t)BT * EMB];      // attention out, fp16
__device__ __half g_wqh[(size_t)QKV_N * EMB];  // W_qkv^T [3072,1024] fp16
__device__ __half g_wph[(size_t)EMB * EMB];    // Wp^T    [1024,1024] fp16

// ---------------------------------------------------------------------------
// PTX helpers (sm_80 baseline features only)
// ---------------------------------------------------------------------------
__device__ __forceinline__ uint32_t smem_to_u32(const void* p) {
    uint32_t a;
    asm("{ .reg .u64 t; cvta.to.shared.u64 t, %1; cvt.u32.u64 %0, t; }" : "=r"(a) : "l"(p));
    return a;
}
__device__ __forceinline__ void cp_async16(uint32_t dst, const void* src) {
    asm volatile("cp.async.cg.shared.global [%0], [%1], 16;" :: "r"(dst), "l"(src));
}
#define CP_COMMIT()  asm volatile("cp.async.commit_group;" ::: "memory")
#define CP_WAIT(n)   asm volatile("cp.async.wait_group %0;" :: "n"(n) : "memory")

// ---------------------------------------------------------------------------
// Producer kernels: round everything the GEMMs consume to fp16.
// ---------------------------------------------------------------------------
__global__ void round_x_kernel(const float4* __restrict__ in,
                               __half2* __restrict__ out, int n4) {
    int i = blockIdx.x * 256 + threadIdx.x;
    if (i >= n4) return;
    float4 v = in[i];
    out[2 * i]     = __floats2half2_rn(v.x, v.y);
    out[2 * i + 1] = __floats2half2_rn(v.z, v.w);
}

// Pack W_qkv^T: row n (0..3071) of [N,K]: n -> (s,h,d); out[n][k] = fp16(W_s[h,k,d])
__global__ void pack_wqkv_kernel(const float* __restrict__ Wq,
                                 const float* __restrict__ Wk,
                                 const float* __restrict__ Wv,
                                 __half* __restrict__ out) {
    int idx = blockIdx.x * 256 + threadIdx.x;
    if (idx >= QKV_N * EMB) return;
    int n = idx >> 10;
    int k = idx & 1023;
    int s = n >> 10;
    int r = n & 1023;
    int h = r >> 6;
    int d = r & 63;
    const float* W = (s == 0) ? Wq : ((s == 1) ? Wk : Wv);
    out[idx] = __float2half_rn(W[((size_t)(h << 10) + k) * HSIZE + d]);
}

// Pack Wp^T: out[n][k] = fp16(Wp[k][n])
__global__ void pack_wp_kernel(const float* __restrict__ Wp,
                               __half* __restrict__ out) {
    int idx = blockIdx.x * 256 + threadIdx.x;
    if (idx >= EMB * EMB) return;
    int n = idx >> 10;
    int k = idx & 1023;
    out[idx] = __float2half_rn(Wp[((size_t)k << 10) + n]);
}

// ---------------------------------------------------------------------------
// fp16 WMMA GEMM: C = A * B^T (+ bias), fp32 accumulate.
// OUT_HALF=false: C fp32 (+optional bias). OUT_HALF=true: C fp16 (no bias).
// CTA tile 128x128, BK=64, 16 K-tiles, cp.async 2-stage pipeline
// (R9-proven issue-then-wait structure), 8 warps (4m x 2n), warp tile 32x64.
// ---------------------------------------------------------------------------
template <bool OUT_HALF>
__global__ __launch_bounds__(256, 2)
void hgemm_kernel(const __half* __restrict__ A,
                  const __half* __restrict__ B,
                  void* __restrict__ Cv,
                  const float* __restrict__ bias,
                  int Ncols) {
    extern __shared__ __align__(16) char smem[];

    const int tid  = threadIdx.x;
    const int wid  = tid >> 5;
    const int lane = tid & 31;
    const int wm   = wid >> 1;     // 0..3  (m)
    const int wn   = wid & 1;      // 0..1  (n)
    const int m0   = blockIdx.y * HBM;
    const int n0   = blockIdx.x * HBN;

    const uint32_t sb32 = smem_to_u32(smem);

    wmma::fragment<wmma::accumulator, 16, 16, 16, float> acc[2][4];
#pragma unroll
    for (int i = 0; i < 2; i++)
#pragma unroll
        for (int j = 0; j < 4; j++) wmma::fill_fragment(acc[i][j], 0.f);

    // cp.async mapping: per matrix, 128 rows x 8 chunks(16B) = 1024 slots.
    const int rA = tid >> 3;       // 0..31
    const int cA = tid & 7;        // 0..7

    auto issue_stage = [&](int t, int s) {
        const int tk = t << 6;     // k offset (elements)
        const uint32_t stg = sb32 + s * STAGEB;
#pragma unroll
        for (int i = 0; i < 4; i++) {
            const int row = rA + i * 32;
            const uint32_t doff = (uint32_t)(row * ROWB + cA * 16);
            cp_async16(stg + doff,
                       A + ((size_t)(m0 + row) << 10) + tk + (cA << 3));
            cp_async16(stg + MATB + doff,
                       B + ((size_t)(n0 + row) << 10) + tk + (cA << 3));
        }
        CP_COMMIT();
    };

    issue_stage(0, 0);

    for (int t = 0; t < NPHYS; t++) {
        const int s = t & 1;
        if (t + 1 < NPHYS) {
            issue_stage(t + 1, s ^ 1);
            CP_WAIT(1);
        } else {
            CP_WAIT(0);
        }
        __syncthreads();

        const __half* sA = (const __half*)(smem + s * STAGEB);
        const __half* sB = (const __half*)(smem + s * STAGEB + MATB);

#pragma unroll
        for (int ks = 0; ks < 4; ks++) {
            const int k0 = ks << 4;
            wmma::fragment<wmma::matrix_a, 16, 16, 16, __half, wmma::row_major> af[2];
#pragma unroll
            for (int mt = 0; mt < 2; mt++)
                wmma::load_matrix_sync(af[mt],
                    sA + (wm * 32 + mt * 16) * ROWE + k0, ROWE);
#pragma unroll
            for (int ng = 0; ng < 4; ng++) {
                wmma::fragment<wmma::matrix_b, 16, 16, 16, __half, wmma::col_major> bf;
                wmma::load_matrix_sync(bf,
                    sB + (wn * 64 + ng * 16) * ROWE + k0, ROWE);
#pragma unroll
                for (int mt = 0; mt < 2; mt++)
                    wmma::mma_sync(acc[mt][ng], af[mt], bf, acc[mt][ng]);
            }
        }
        __syncthreads();
    }

    // Epilogue
    if (!OUT_HALF && bias == nullptr) {
        float* C = (float*)Cv;
#pragma unroll
        for (int mt = 0; mt < 2; mt++)
#pragma unroll
            for (int ng = 0; ng < 4; ng++) {
                int r0 = m0 + wm * 32 + mt * 16;
                int c0 = n0 + wn * 64 + ng * 16;
                wmma::store_matrix_sync(C + (size_t)r0 * Ncols + c0,
                                        acc[mt][ng], Ncols, wmma::mem_row_major);
            }
    } else {
        // Per-warp smem staging (aliased onto tile buffers; safe after final sync)
        float* stg = (float*)(smem) + wid * 16 * 20;   // 16x16 tile, ld=20
#pragma unroll
        for (int mt = 0; mt < 2; mt++)
#pragma unroll
            for (int ng = 0; ng < 4; ng++) {
                wmma::store_matrix_sync(stg, acc[mt][ng], 20, wmma::mem_row_major);
                __syncwarp();
                int r0 = m0 + wm * 32 + mt * 16;
                int c0 = n0 + wn * 64 + ng * 16;
                int rr = lane >> 1;
                int ch = (lane & 1) << 3;              // 0 or 8
                const float* srow = stg + rr * 20 + ch;
                if (OUT_HALF) {
                    __half* Ch = (__half*)Cv;
                    union { uint4 u; __half2 h[4]; } pk;
                    pk.h[0] = __floats2half2_rn(srow[0], srow[1]);
                    pk.h[1] = __floats2half2_rn(srow[2], srow[3]);
                    pk.h[2] = __floats2half2_rn(srow[4], srow[5]);
                    pk.h[3] = __floats2half2_rn(srow[6], srow[7]);
                    *(uint4*)(Ch + (size_t)(r0 + rr) * Ncols + c0 + ch) = pk.u;
                } else {
                    float* C = (float*)Cv;
                    float4 v0, v1;
                    v0.x = srow[0] + bias[c0 + ch + 0];
                    v0.y = srow[1] + bias[c0 + ch + 1];
                    v0.z = srow[2] + bias[c0 + ch + 2];
                    v0.w = srow[3] + bias[c0 + ch + 3];
                    v1.x = srow[4] + bias[c0 + ch + 4];
                    v1.y = srow[5] + bias[c0 + ch + 5];
                    v1.z = srow[6] + bias[c0 + ch + 6];
                    v1.w = srow[7] + bias[c0 + ch + 7];
                    *(float4*)(C + (size_t)(r0 + rr) * Ncols + c0 + ch)     = v0;
                    *(float4*)(C + (size_t)(r0 + rr) * Ncols + c0 + ch + 4) = v1;
                }
                __syncwarp();
            }
    }
}

// ---------------------------------------------------------------------------
// Attention core: one block per (batch, head). 128 threads.
// qkv: [BT, 3072] fp16 (vectorized half2 loads). Compute fp32.
// Output: fp16 head-concat [BT, 1024].
// ---------------------------------------------------------------------------
__global__ __launch_bounds__(128)
void attn_kernel(const __half* __restrict__ qkv,
                 __half* __restrict__ yh) {
    __shared__ float qs[SEQ][HSIZE + 2];
    __shared__ float ks[SEQ][HSIZE + 2];
    __shared__ float vs[SEQ][HSIZE + 2];
    __shared__ float ss[SEQ][SEQ + 1];

    const int bh = blockIdx.x;
    const int b  = bh >> 4;
    const int h  = bh & 15;
    const int tid = threadIdx.x;

    const __half* base = qkv + (size_t)b * SEQ * QKV_N + h * HSIZE;

    // 32 rows x 32 half2-chunks = 1024 slots; each thread does 8 (coalesced).
    for (int idx = tid; idx < SEQ * (HSIZE / 2); idx += 128) {
        int t = idx >> 5;           // row 0..31
        int c = idx & 31;           // half2 chunk 0..31
        const __half* rp = base + (size_t)t * QKV_N + 2 * c;
        float2 q2 = __half22float2(*(const __half2*)(rp));
        float2 k2 = __half22float2(*(const __half2*)(rp + EMB));
        float2 v2 = __half22float2(*(const __half2*)(rp + 2 * EMB));
        qs[t][2 * c] = q2.x; qs[t][2 * c + 1] = q2.y;
        ks[t][2 * c] = k2.x; ks[t][2 * c + 1] = k2.y;
        vs[t][2 * c] = v2.x; vs[t][2 * c + 1] = v2.y;
    }
    __syncthreads();

    for (int e = tid; e < SEQ * SEQ; e += 128) {
        int i = e >> 5;
        int j = e & 31;
        float acc = 0.f;
        if (j <= i) {
#pragma unroll
            for (int d = 0; d < HSIZE; d++) acc += qs[i][d] * ks[j][d];
            acc *= 0.125f;
        }
        ss[i][j] = acc;
    }
    __syncthreads();

    if (tid < SEQ) {
        const int i = tid;
        float mx = -1e30f;
        for (int j = 0; j <= i; j++) mx = fmaxf(mx, ss[i][j]);
        float sum = 0.f;
        for (int j = 0; j <= i; j++) {
            float ev = __expf(ss[i][j] - mx);
            ss[i][j] = ev;
            sum += ev;
        }
        float inv = 1.f / sum;
        for (int j = 0; j <= i; j++) ss[i][j] *= inv;
        for (int j = i + 1; j < SEQ; j++) ss[i][j] = 0.f;
    }
    __syncthreads();

    // out = att @ v; write as half2 (coalesced, vectorized)
    for (int idx = tid; idx < SEQ * (HSIZE / 2); idx += 128) {
        int i = idx >> 5;
        int c = idx & 31;
        int d = 2 * c;
        float a0 = 0.f, a1 = 0.f;
#pragma unroll
        for (int j = 0; j < SEQ; j++) {
            float p = ss[i][j];
            a0 += p * vs[j][d];
            a1 += p * vs[j][d + 1];
        }
        size_t off = ((size_t)b * SEQ + i) * EMB + h * HSIZE + d;
        *(__half2*)(yh + off) = __floats2half2_rn(a0, a1);
    }
}

// ---------------------------------------------------------------------------
// Launch
// ---------------------------------------------------------------------------
extern "C" void kernel_launch(void* const* d_in, const int* in_sizes, int n_in,
                              void* d_out, int out_size) {
    const float* x  = (const float*)d_in[0];   // [2048, 32, 1024]
    const float* Wq = (const float*)d_in[1];   // [16, 1024, 64]
    const float* Wk = (const float*)d_in[2];
    const float* Wv = (const float*)d_in[3];
    const float* Wp = (const float*)d_in[4];   // [1024, 1024]
    const float* bp = (const float*)d_in[5];   // [1024]
    float* out = (float*)d_out;                // [2048, 32, 1024]

    __half *qkvh, *xh, *yh, *wqh, *wph;
    cudaGetSymbolAddress((void**)&qkvh, g_qkvh);
    cudaGetSymbolAddress((void**)&xh,   g_xh);
    cudaGetSymbolAddress((void**)&yh,   g_yh);
    cudaGetSymbolAddress((void**)&wqh,  g_wqh);
    cudaGetSymbolAddress((void**)&wph,  g_wph);

    cudaFuncSetAttribute(hgemm_kernel<true>,
                         cudaFuncAttributeMaxDynamicSharedMemorySize, SMEMB);
    cudaFuncSetAttribute(hgemm_kernel<false>,
                         cudaFuncAttributeMaxDynamicSharedMemorySize, SMEMB);

    // 0. Round x to fp16
    {
        int n4 = (BT * EMB) / 4;
        round_x_kernel<<<n4 / 256, 256>>>((const float4*)x, (__half2*)xh, n4);
    }
    // 1. Pack weight transposes (fp16)
    pack_wqkv_kernel<<<(QKV_N * EMB) / 256, 256>>>(Wq, Wk, Wv, wqh);
    pack_wp_kernel<<<(EMB * EMB) / 256, 256>>>(Wp, wph);

    // 2. QKV projection: [65536,1024] x [1024,3072] -> fp16 qkv
    {
        dim3 grid(QKV_N / HBN, BT / HBM);   // (24, 512)
        hgemm_kernel<true><<<grid, 256, SMEMB>>>(xh, wqh, qkvh, nullptr, QKV_N);
    }
    // 3. Attention per (b, h); fp16 in, fp16 out
    attn_kernel<<<BATCH * HEADS, 128>>>(qkvh, yh);

    // 4. Output projection + bias: [65536,1024] x [1024,1024] -> fp32 out
    {
        dim3 grid(EMB / HBN, BT / HBM);     // (8, 512)
        hgemm_kernel<false><<<grid, 256, SMEMB>>>(yh, wph, out, bp, EMB);
    }
}